// round 8
// baseline (speedup 1.0000x reference)
#include <cuda_runtime.h>

// out[b,k] = tanh( sum_n W[k,n] * x[b,k,n] )
// B=64, K=4096, N=256 (fp32).
//
// Half-warp variant of the R1 roofline kernel: lanes 0-15 own row 2w,
// lanes 16-31 own row 2w+1. Identical compulsory byte traffic and full
// 128B-sector coalescing (each LDG.128 covers two contiguous 512B runs),
// but the reduction is 4 SHFL levels instead of 5 and each warp writes
// two outputs — ~15% fewer issued instructions per byte streamed.

#define GK 4096
#define GN 256

__global__ __launch_bounds__(256, 8)
void ginn_halfwarp_kernel(const float* __restrict__ x,
                          const float* __restrict__ W,
                          float* __restrict__ out,
                          int total_outputs) {
    const int warp = (blockIdx.x * blockDim.x + threadIdx.x) >> 5;
    const int lane = threadIdx.x & 31;
    const int half = lane >> 4;          // 0 or 1
    const int hl   = lane & 15;          // lane within half-warp

    const int row = warp * 2 + half;     // this half-warp's output row
    if (row >= total_outputs) return;

    const int k = row & (GK - 1);

    // Row = 256 floats = 64 float4. 16 lanes x 4 float4 each.
    const float4* __restrict__ xp =
        reinterpret_cast<const float4*>(x + (size_t)row * GN);
    const float4* __restrict__ wp =
        reinterpret_cast<const float4*>(W + (size_t)k * GN);

    // Front-batch all 8 loads (4 x-f4 + 4 W-f4 per lane).
    const float4 x0 = xp[hl];
    const float4 x1 = xp[hl + 16];
    const float4 x2 = xp[hl + 32];
    const float4 x3 = xp[hl + 48];
    const float4 w0 = __ldg(wp + hl);
    const float4 w1 = __ldg(wp + hl + 16);
    const float4 w2 = __ldg(wp + hl + 32);
    const float4 w3 = __ldg(wp + hl + 48);

    float s = x0.x * w0.x;
    s = fmaf(x0.y, w0.y, s); s = fmaf(x0.z, w0.z, s); s = fmaf(x0.w, w0.w, s);
    s = fmaf(x1.x, w1.x, s); s = fmaf(x1.y, w1.y, s);
    s = fmaf(x1.z, w1.z, s); s = fmaf(x1.w, w1.w, s);
    s = fmaf(x2.x, w2.x, s); s = fmaf(x2.y, w2.y, s);
    s = fmaf(x2.z, w2.z, s); s = fmaf(x2.w, w2.w, s);
    s = fmaf(x3.x, w3.x, s); s = fmaf(x3.y, w3.y, s);
    s = fmaf(x3.z, w3.z, s); s = fmaf(x3.w, w3.w, s);

    // Butterfly over 16 lanes (stays within each half-warp): 4 levels.
    #pragma unroll
    for (int off = 8; off > 0; off >>= 1)
        s += __shfl_xor_sync(0xffffffffu, s, off);

    if (hl == 0)
        out[row] = tanhf(s);
}

extern "C" void kernel_launch(void* const* d_in, const int* in_sizes, int n_in,
                              void* d_out, int out_size) {
    const float* x = (const float*)d_in[0];  // [B, K, N] fp32
    const float* W = (const float*)d_in[1];  // [K, N] fp32
    float* out = (float*)d_out;              // [B, K] fp32

    const int total_outputs = out_size;      // B*K = 262144
    const int threads = 256;                 // 8 warps -> 16 outputs/block
    const int outputs_per_block = (threads / 32) * 2;
    const int blocks = (total_outputs + outputs_per_block - 1) / outputs_per_block;

    ginn_halfwarp_kernel<<<blocks, threads>>>(x, W, out, total_outputs);
}

// round 9
// speedup vs baseline: 1.0007x; 1.0007x over previous
#include <cuda_runtime.h>

// out[b,k] = tanh( sum_n W[k,n] * x[b,k,n] )
// B=64, K=4096, N=256 (fp32). One warp per (b,k) output row.
//
// FINAL — roofline-optimal. Eight structural variants (2-row MLP-deep,
// W-in-registers, contiguous per-SM streams, cache hints, persistent
// pipeline, half-warp reduce) all move exactly the compulsory 276 MB and pin
// at 6.4-6.55 TB/s (80-82.6% of 8 TB/s spec). This simplest form measures
// highest (82.6% DRAM, 42.4us ncu): one fresh warp per row has zero
// load-dependencies, so 221 CTA waves keep the chip-wide LDG queue
// saturated and the CTA scheduler pipelines the stream for free.
// Issue slack (36%), occupancy, and instruction count are all non-binding:
// the HBM controller is the sole limiter.

#define GK 4096
#define GN 256

__global__ __launch_bounds__(256, 8)
void ginn_input_kernel(const float* __restrict__ x,
                       const float* __restrict__ W,
                       float* __restrict__ out,
                       int total_outputs) {
    int warp = (blockIdx.x * blockDim.x + threadIdx.x) >> 5;
    int lane = threadIdx.x & 31;
    if (warp >= total_outputs) return;

    int k = warp & (GK - 1);  // K = 4096 (power of 2)

    const float4* __restrict__ xp =
        reinterpret_cast<const float4*>(x + (size_t)warp * GN);
    const float4* __restrict__ wp =
        reinterpret_cast<const float4*>(W + (size_t)k * GN);

    // 256 floats = 64 float4; 32 lanes * 2, all 4 loads front-batched.
    float4 x0 = xp[lane];
    float4 w0 = wp[lane];
    float4 x1 = xp[lane + 32];
    float4 w1 = wp[lane + 32];

    float s = x0.x * w0.x;
    s = fmaf(x0.y, w0.y, s);
    s = fmaf(x0.z, w0.z, s);
    s = fmaf(x0.w, w0.w, s);
    s = fmaf(x1.x, w1.x, s);
    s = fmaf(x1.y, w1.y, s);
    s = fmaf(x1.z, w1.z, s);
    s = fmaf(x1.w, w1.w, s);

    // butterfly reduce across the warp
    #pragma unroll
    for (int off = 16; off > 0; off >>= 1)
        s += __shfl_xor_sync(0xffffffffu, s, off);

    if (lane == 0)
        out[warp] = tanhf(s);
}

extern "C" void kernel_launch(void* const* d_in, const int* in_sizes, int n_in,
                              void* d_out, int out_size) {
    const float* x = (const float*)d_in[0];  // [B, K, N] fp32
    const float* W = (const float*)d_in[1];  // [K, N] fp32
    float* out = (float*)d_out;              // [B, K] fp32

    const int total_outputs = out_size;      // B*K = 262144
    const int threads = 256;                 // 8 warps/block -> 8 outputs/block
    const int warps_per_block = threads / 32;
    const int blocks = (total_outputs + warps_per_block - 1) / warps_per_block;

    ginn_input_kernel<<<blocks, threads>>>(x, W, out, total_outputs);
}

// round 10
// speedup vs baseline: 1.0066x; 1.0059x over previous
#include <cuda_runtime.h>

// out[b,k] = tanh( sum_n W[k,n] * x[b,k,n] )
// B=64, K=4096, N=256 (fp32). One warp per (b,k) output row.
//
// FINAL — roofline-optimal at the achieved-HBM wall.
// Nine rounds of evidence: all correct structural variants (2-row MLP-deep,
// W-in-registers, contiguous per-SM streams, cache hints, persistent
// pipeline, half-warp reduce) move exactly the compulsory 276 MB and land
// in a 42.4-43.4us band = run-to-run noise (+/-0.6us on identical source).
// DRAM pins at 6.4-6.55 TB/s (81-82.6% of spec) regardless of access
// pattern; issue slack, occupancy, instruction count, and L2 traffic are
// all proven non-binding. One fresh dependency-free warp per row lets the
// CTA scheduler saturate the chip-wide LDG queue for free; anything that
// adds loop-carried dependencies (R6 pipeline) regresses 2.6x.

#define GK 4096
#define GN 256

__global__ __launch_bounds__(256, 8)
void ginn_input_kernel(const float* __restrict__ x,
                       const float* __restrict__ W,
                       float* __restrict__ out,
                       int total_outputs) {
    int warp = (blockIdx.x * blockDim.x + threadIdx.x) >> 5;
    int lane = threadIdx.x & 31;
    if (warp >= total_outputs) return;

    int k = warp & (GK - 1);  // K = 4096 (power of 2)

    const float4* __restrict__ xp =
        reinterpret_cast<const float4*>(x + (size_t)warp * GN);
    const float4* __restrict__ wp =
        reinterpret_cast<const float4*>(W + (size_t)k * GN);

    // 256 floats = 64 float4; 32 lanes * 2, all 4 loads front-batched.
    float4 x0 = xp[lane];
    float4 w0 = wp[lane];
    float4 x1 = xp[lane + 32];
    float4 w1 = wp[lane + 32];

    float s = x0.x * w0.x;
    s = fmaf(x0.y, w0.y, s);
    s = fmaf(x0.z, w0.z, s);
    s = fmaf(x0.w, w0.w, s);
    s = fmaf(x1.x, w1.x, s);
    s = fmaf(x1.y, w1.y, s);
    s = fmaf(x1.z, w1.z, s);
    s = fmaf(x1.w, w1.w, s);

    // butterfly reduce across the warp
    #pragma unroll
    for (int off = 16; off > 0; off >>= 1)
        s += __shfl_xor_sync(0xffffffffu, s, off);

    if (lane == 0)
        out[warp] = tanhf(s);
}

extern "C" void kernel_launch(void* const* d_in, const int* in_sizes, int n_in,
                              void* d_out, int out_size) {
    const float* x = (const float*)d_in[0];  // [B, K, N] fp32
    const float* W = (const float*)d_in[1];  // [K, N] fp32
    float* out = (float*)d_out;              // [B, K] fp32

    const int total_outputs = out_size;      // B*K = 262144
    const int threads = 256;                 // 8 warps/block -> 8 outputs/block
    const int warps_per_block = threads / 32;
    const int blocks = (total_outputs + warps_per_block - 1) / warps_per_block;

    ginn_input_kernel<<<blocks, threads>>>(x, W, out, total_outputs);
}

// round 11
// speedup vs baseline: 1.0081x; 1.0015x over previous
#include <cuda_runtime.h>

// out[b,k] = tanh( sum_n W[k,n] * x[b,k,n] )
// B=64, K=4096, N=256 (fp32). One warp per (b,k) output row.
//
// FINAL — roofline-optimal at the achieved-HBM wall.
// Ten rounds of evidence. Compulsory traffic: 268 MB x + 4 MB W + 1 MB out
// = 276 MB; measured at 6.4-6.55 TB/s (80-82.6% of 8 TB/s spec) across every
// correct structural variant (2-row MLP-deep, W-in-registers, contiguous
// per-SM streams, cache hints, persistent pipeline, half-warp reduce), all
// landing in a 42.4-43.4us band equal to run-to-run noise (+/-0.6us on
// identical source, R7/R9/R10). Issue slack (36%), occupancy (45-83%),
// instruction count, L2-crossbar traffic (halved in R3, no effect), and
// per-SM stream locality are all proven non-binding: the HBM read-stream
// ceiling is the sole limiter and is access-pattern-independent.
// One fresh dependency-free warp per row lets the CTA scheduler saturate
// the chip-wide LDG queue for free; adding loop-carried load dependencies
// (R6 persistent pipeline) regresses 2.6x.

#define GK 4096
#define GN 256

__global__ __launch_bounds__(256, 8)
void ginn_input_kernel(const float* __restrict__ x,
                       const float* __restrict__ W,
                       float* __restrict__ out,
                       int total_outputs) {
    int warp = (blockIdx.x * blockDim.x + threadIdx.x) >> 5;
    int lane = threadIdx.x & 31;
    if (warp >= total_outputs) return;

    int k = warp & (GK - 1);  // K = 4096 (power of 2)

    const float4* __restrict__ xp =
        reinterpret_cast<const float4*>(x + (size_t)warp * GN);
    const float4* __restrict__ wp =
        reinterpret_cast<const float4*>(W + (size_t)k * GN);

    // 256 floats = 64 float4; 32 lanes * 2, all 4 loads front-batched.
    float4 x0 = xp[lane];
    float4 w0 = wp[lane];
    float4 x1 = xp[lane + 32];
    float4 w1 = wp[lane + 32];

    float s = x0.x * w0.x;
    s = fmaf(x0.y, w0.y, s);
    s = fmaf(x0.z, w0.z, s);
    s = fmaf(x0.w, w0.w, s);
    s = fmaf(x1.x, w1.x, s);
    s = fmaf(x1.y, w1.y, s);
    s = fmaf(x1.z, w1.z, s);
    s = fmaf(x1.w, w1.w, s);

    // butterfly reduce across the warp
    #pragma unroll
    for (int off = 16; off > 0; off >>= 1)
        s += __shfl_xor_sync(0xffffffffu, s, off);

    if (lane == 0)
        out[warp] = tanhf(s);
}

extern "C" void kernel_launch(void* const* d_in, const int* in_sizes, int n_in,
                              void* d_out, int out_size) {
    const float* x = (const float*)d_in[0];  // [B, K, N] fp32
    const float* W = (const float*)d_in[1];  // [K, N] fp32
    float* out = (float*)d_out;              // [B, K] fp32

    const int total_outputs = out_size;      // B*K = 262144
    const int threads = 256;                 // 8 warps/block -> 8 outputs/block
    const int warps_per_block = threads / 32;
    const int blocks = (total_outputs + warps_per_block - 1) / warps_per_block;

    ginn_input_kernel<<<blocks, threads>>>(x, W, out, total_outputs);
}